// round 4
// baseline (speedup 1.0000x reference)
#include <cuda_runtime.h>

// Shapes fixed by the problem: N=8192, D=64.
#define N_ROWS 8192
#define D_DIM  64

#define COLS4    (N_ROWS / 4)   // 2048 float4 per row
#define THREADS  256
#define TILE     256            // 256x256 output tile per block
#define NTILES   (N_ROWS / TILE) // 32

__device__ __forceinline__ float leaky(float e) {
    // e >= 0 ? e : 0.2*e  ==  max(e, 0.2*e) for all e
    return fmaxf(e, 0.2f * e);
}

__device__ __forceinline__ float4 row_vals(float s1, float4 s2) {
    float4 e;
    e.x = leaky(s1 + s2.x);
    e.y = leaky(s1 + s2.y);
    e.z = leaky(s1 + s2.z);
    e.w = leaky(s1 + s2.w);
    return e;
}

// Fused kernel: each block owns a 256x256 output tile.
// Phase 1: recompute the 256 s1 values (rows) and 256 s2 values (cols) this
//          tile needs, straight from Wh (L2-resident, 2MB) into smem.
// Phase 2: stream the tile out with 128-bit evict-first stores.
__global__ __launch_bounds__(THREADS) void fused_kernel(
        const float* __restrict__ Wh,
        const float* __restrict__ a,
        float4* __restrict__ out) {
    __shared__ float sh_s1[TILE];
    __shared__ float sh_s2[TILE];

    const int t    = threadIdx.x;
    const int col0 = blockIdx.x * TILE;
    const int row0 = blockIdx.y * TILE;

    // ---- Phase 1: two 64-long dot products per thread ----
    {
        const float4* w1 = reinterpret_cast<const float4*>(Wh + (size_t)(row0 + t) * D_DIM);
        const float4* w2 = reinterpret_cast<const float4*>(Wh + (size_t)(col0 + t) * D_DIM);
        const float4* a1 = reinterpret_cast<const float4*>(a);
        const float4* a2 = reinterpret_cast<const float4*>(a + D_DIM);

        float acc1 = 0.f, acc2 = 0.f;
        #pragma unroll
        for (int i = 0; i < D_DIM / 4; i++) {
            float4 x = w1[i], y = a1[i];
            acc1 += x.x * y.x + x.y * y.y + x.z * y.z + x.w * y.w;
            float4 p = w2[i], q = a2[i];
            acc2 += p.x * q.x + p.y * q.y + p.z * q.z + p.w * q.w;
        }
        sh_s1[t] = acc1;
        sh_s2[t] = acc2;
    }
    __syncthreads();

    // ---- Phase 2: stream the 256x256 tile ----
    // 64 col-groups (float4) x 4 row-groups of 64 rows each.
    const int c4 = t & 63;        // which float4 column within the tile
    const int rg = t >> 6;        // row group 0..3

    const float4 s2 = reinterpret_cast<const float4*>(sh_s2)[c4];
    const float* s1p = sh_s1 + rg * 64;

    float4* dst = out + (size_t)(row0 + rg * 64) * COLS4 + (col0 >> 2) + c4;

    #pragma unroll 4
    for (int r = 0; r < 64; r += 4) {
        float a0 = s1p[r + 0];
        float a1v = s1p[r + 1];
        float a2v = s1p[r + 2];
        float a3 = s1p[r + 3];

        __stcs(dst + 0 * (size_t)COLS4, row_vals(a0,  s2));
        __stcs(dst + 1 * (size_t)COLS4, row_vals(a1v, s2));
        __stcs(dst + 2 * (size_t)COLS4, row_vals(a2v, s2));
        __stcs(dst + 3 * (size_t)COLS4, row_vals(a3,  s2));
        dst += 4 * (size_t)COLS4;
    }
}

extern "C" void kernel_launch(void* const* d_in, const int* in_sizes, int n_in,
                              void* d_out, int out_size) {
    const float* Wh = (const float*)d_in[0];
    const float* a  = (const float*)d_in[1];
    float4* out = (float4*)d_out;

    dim3 grid(NTILES, NTILES);   // 32 x 32 = 1024 blocks
    fused_kernel<<<grid, THREADS>>>(Wh, a, out);
}